// round 8
// baseline (speedup 1.0000x reference)
#include <cuda_runtime.h>
#include <stdint.h>

#define NC    32
#define KC    16
#define DSUB  128
#define INF   4096
#define OF    2048
#define MAXTOK 2048

typedef unsigned long long ull;

__device__ float         g_lut[NC * KC * OF];
__device__ unsigned char g_idx[MAXTOK * NC];

// ---- packed f32x2 helpers --------------------------------------------------
__device__ __forceinline__ ull pk2(float x, float y) {
    ull r; asm("mov.b64 %0, {%1,%2};" : "=l"(r) : "f"(x), "f"(y)); return r;
}
__device__ __forceinline__ void upk2(ull v, float& x, float& y) {
    asm("mov.b64 {%0,%1}, %2;" : "=f"(x), "=f"(y) : "l"(v));
}
__device__ __forceinline__ ull fma2(ull a, ull b, ull c) {
    ull d; asm("fma.rn.f32x2 %0, %1, %2, %3;" : "=l"(d) : "l"(a), "l"(b), "l"(c)); return d;
}
__device__ __forceinline__ void lds_v2u64(ull& a, ull& b, const float* p) {
    asm("{ .reg .u64 t; cvta.to.shared.u64 t, %2; ld.shared.v2.u64 {%0,%1}, [t]; }"
        : "=l"(a), "=l"(b) : "l"(p));
}

// smem layout for idx (floats)
#define XS_STRIDE 132
#define IDX_XS    (128 * XS_STRIDE)
#define IDX_CST   (DSUB * KC)
#define IDX_RED   (128 * 17)
#define IDX_C2P   128
#define IDX_C2S   16
#define IDX_FLOATS (IDX_XS + IDX_CST + IDX_RED + IDX_C2P + IDX_C2S)

// ---------------------------------------------------------------------------
// K2: idx[token][c] = argmin_k ( c2[k] - 2 * <x_sub, cent_k> )
// v4: __launch_bounds__(256, 2) — smem caps us at 2 CTAs/SM anyway, so give
// ptxas the full 128-reg budget. This lets the two 8-deep float4 LDG batches
// actually stay register-resident (R7 compiled to 40 regs -> ~2-deep -> only
// 640 GB/s). Compute loop packed as fma2 (bitwise-identical per-k chains).
// ---------------------------------------------------------------------------
__global__ __launch_bounds__(256, 2) void idx_kernel(const float* __restrict__ x,
                                                     const float* __restrict__ cent)
{
    extern __shared__ float sm[];
    float* xs  = sm;                     // [128][XS_STRIDE]
    float* cst = sm + IDX_XS;            // [DSUB][KC]
    float* red = cst + IDX_CST;          // [128][17]
    float* c2p = red + IDX_RED;          // [16][8]
    float* c2s = c2p + IDX_C2P;          // [16]

    const int c   = blockIdx.y;
    const int tb  = blockIdx.x * 128;
    const int tid = threadIdx.x;

    // stage x tile: two 8-deep batches of independent LDG.128, then the STS.
#pragma unroll
    for (int b = 0; b < 2; b++) {
        float4 buf[8];
#pragma unroll
        for (int j = 0; j < 8; j++) {
            int i   = tid + (b * 8 + j) * 256;
            int row = i >> 5;
            int col = (i & 31) * 4;
            buf[j] = *(const float4*)&x[(size_t)(tb + row) * INF + c * DSUB + col];
        }
#pragma unroll
        for (int j = 0; j < 8; j++) {
            int i   = tid + (b * 8 + j) * 256;
            int row = i >> 5;
            int col = (i & 31) * 4;
            *(float4*)&xs[row * XS_STRIDE + col] = buf[j];
        }
    }
    for (int i = tid; i < KC * DSUB; i += 256) {
        int k = i >> 7, d = i & 127;
        cst[d * KC + k] = cent[(c * KC + k) * DSUB + d];
    }
    __syncthreads();

    if (tid < 128) {
        int k = tid >> 3, part = tid & 7;
        float s = 0.f;
        for (int d = part * 16; d < part * 16 + 16; d++) {
            float cv = cst[d * KC + k];
            s = fmaf(cv, cv, s);
        }
        c2p[k * 8 + part] = s;
    }
    __syncthreads();
    if (tid < 16) {
        float s = 0.f;
        for (int p = 0; p < 8; p++) s += c2p[tid * 8 + p];
        c2s[tid] = s;
    }
    __syncthreads();

    const int token = tid & 127;
    const int half  = tid >> 7;
    const int dbase = half * 64;

    // packed accumulators: acc2[p] holds (k=2p, k=2p+1); per-k chain order is
    // identical to the scalar version -> bitwise-same dot products.
    ull acc2[8];
#pragma unroll
    for (int p = 0; p < 8; p++) acc2[p] = 0ull;

    const float* xr = &xs[token * XS_STRIDE];
    for (int d0 = dbase; d0 < dbase + 64; d0 += 4) {
        float4 xq = *(const float4*)&xr[d0];
        float xv4[4] = {xq.x, xq.y, xq.z, xq.w};
#pragma unroll
        for (int j = 0; j < 4; j++) {
            ull xp = pk2(xv4[j], xv4[j]);
            const float* cp = &cst[(d0 + j) * KC];
            ull a0, a1, a2, a3;
            lds_v2u64(a0, a1, cp);        // k0..k3
            lds_v2u64(a2, a3, cp + 4);    // k4..k7
            acc2[0] = fma2(a0, xp, acc2[0]);
            acc2[1] = fma2(a1, xp, acc2[1]);
            acc2[2] = fma2(a2, xp, acc2[2]);
            acc2[3] = fma2(a3, xp, acc2[3]);
            lds_v2u64(a0, a1, cp + 8);    // k8..k11
            lds_v2u64(a2, a3, cp + 12);   // k12..k15
            acc2[4] = fma2(a0, xp, acc2[4]);
            acc2[5] = fma2(a1, xp, acc2[5]);
            acc2[6] = fma2(a2, xp, acc2[6]);
            acc2[7] = fma2(a3, xp, acc2[7]);
        }
    }

    float acc[KC];
#pragma unroll
    for (int p = 0; p < 8; p++) upk2(acc2[p], acc[p * 2], acc[p * 2 + 1]);

    if (half == 1) {
#pragma unroll
        for (int k = 0; k < KC; k++) red[token * 17 + k] = acc[k];
    }
    __syncthreads();
    if (half == 0) {
        float best = 1e30f, second = 1e30f;
        int bi = 0, si = 0;
#pragma unroll
        for (int k = 0; k < KC; k++) {
            float dot = acc[k] + red[token * 17 + k];
            float v = c2s[k] - 2.f * dot;
            if (v < best)        { second = best; si = bi; best = v; bi = k; }
            else if (v < second) { second = v; si = k; }
        }
        if (second - best < 1e-3f) {
            double vb = 0.0, vs = 0.0;
            for (int d = 0; d < DSUB; d++) {
                double xv = (double)xr[d];
                double cb = (double)cst[d * KC + bi];
                double cs = (double)cst[d * KC + si];
                vb += cb * (cb - 2.0 * xv);
                vs += cs * (cs - 2.0 * xv);
            }
            if (vs < vb || (vs == vb && si < bi)) bi = si;
        }
        g_idx[(size_t)(tb + token) * NC + c] = (unsigned char)bi;
    }
}

// ---------------------------------------------------------------------------
// K1: lut — EXACT Round-5 version (unchanged).
// ---------------------------------------------------------------------------
__global__ __launch_bounds__(512) void lut_kernel(const float* __restrict__ cent,
                                                  const float* __restrict__ weight)
{
    __shared__ float cst[DSUB * KC];
    __shared__ float red[3][KC][128];

    const int c   = blockIdx.y;
    const int tid = threadIdx.x;
    const int dq  = tid >> 7;
    const int col = tid & 127;

    for (int i = tid; i < KC * DSUB; i += 512) {
        int k = i >> 7, d = i & 127;
        cst[d * KC + k] = cent[(c * KC + k) * DSUB + d];
    }
    __syncthreads();

    const int o = blockIdx.x * 128 + col;
    const float* wp = weight + (size_t)c * DSUB * OF + o + (size_t)(dq * 32) * OF;

    ull acc[8];
#pragma unroll
    for (int p = 0; p < 8; p++) acc[p] = 0ull;

#pragma unroll
    for (int half = 0; half < 2; half++) {
        float w[16];
#pragma unroll
        for (int i = 0; i < 16; i++) w[i] = wp[(size_t)(half * 16 + i) * OF];
#pragma unroll
        for (int i = 0; i < 16; i++) {
            ull wv = pk2(w[i], w[i]);
            const float* cp = &cst[(dq * 32 + half * 16 + i) * KC];
            ull a0, a1, a2, a3;
            lds_v2u64(a0, a1, cp);
            lds_v2u64(a2, a3, cp + 8);
            acc[0] = fma2(a0, wv, acc[0]);
            acc[1] = fma2(a1, wv, acc[1]);
            acc[2] = fma2(a2, wv, acc[2]);
            acc[3] = fma2(a3, wv, acc[3]);
            lds_v2u64(a0, a1, cp + 4);
            acc[4] = fma2(a0, wv, acc[4]);
            acc[5] = fma2(a1, wv, acc[5]);
            lds_v2u64(a2, a3, cp + 12);
            acc[6] = fma2(a2, wv, acc[6]);
            acc[7] = fma2(a3, wv, acc[7]);
        }
    }

    const int kmap[8] = {0, 1, 4, 5, 2, 3, 6, 7};

    if (dq != 0) {
#pragma unroll
        for (int p = 0; p < 8; p++) {
            float v0, v1; upk2(acc[p], v0, v1);
            int kp = kmap[p];
            red[dq - 1][kp * 2 + 0][col] = v0;
            red[dq - 1][kp * 2 + 1][col] = v1;
        }
    }
    __syncthreads();
    if (dq == 0) {
#pragma unroll
        for (int p = 0; p < 8; p++) {
            float v0, v1; upk2(acc[p], v0, v1);
            int k0 = kmap[p] * 2, k1 = k0 + 1;
            v0 = v0 + red[0][k0][col] + red[1][k0][col] + red[2][k0][col];
            v1 = v1 + red[0][k1][col] + red[1][k1][col] + red[2][k1][col];
            g_lut[(size_t)(c * KC + k0) * OF + o] = v0;
            g_lut[(size_t)(c * KC + k1) * OF + o] = v1;
        }
    }
}

// ---------------------------------------------------------------------------
// K3: gather — EXACT Round-4 version (unchanged).
// ---------------------------------------------------------------------------
__global__ __launch_bounds__(256) void gather_kernel(float* __restrict__ out,
                                                     const float* __restrict__ bias)
{
    extern __shared__ float sm[];
    float*         lut_s = sm;
    unsigned char* idx_s = (unsigned char*)(sm + NC * KC * 32);

    const int ob  = blockIdx.x * 32;
    const int tb  = blockIdx.y * 256;
    const int tid = threadIdx.x;

    for (int i = tid; i < NC * KC * 32 / 4; i += 256) {
        int row = i >> 3;
        int col = (i & 7) * 4;
        float4 v = *(const float4*)&g_lut[(size_t)row * OF + ob + col];
        *(float4*)&lut_s[row * 32 + col] = v;
    }
    {
        const uint4* src = (const uint4*)&g_idx[(size_t)tb * NC];
        uint4* dst = (uint4*)idx_s;
        for (int i = tid; i < (256 * NC) / 16; i += 256) dst[i] = src[i];
    }
    __syncthreads();

    const int oi = tid & 31;
    const int tg = tid >> 5;
    const float bv = bias[ob + oi];

    for (int t = tg; t < 256; t += 8) {
        uint4 a = *(const uint4*)&idx_s[t * NC];
        uint4 b = *(const uint4*)&idx_s[t * NC + 16];
        unsigned int iw[8] = {a.x, a.y, a.z, a.w, b.x, b.y, b.z, b.w};
        float s0 = 0.f, s1 = 0.f;
#pragma unroll
        for (int c = 0; c < NC; c++) {
            unsigned int k = (iw[c >> 2] >> ((c & 3) * 8)) & 0xFFu;
            float v = lut_s[(c * KC + k) * 32 + oi];
            if (c & 1) s1 += v;
            else       s0 += v;
        }
        out[(size_t)(tb + t) * OF + ob + oi] = s0 + s1 + bv;
    }
}

// ---------------------------------------------------------------------------
extern "C" void kernel_launch(void* const* d_in, const int* in_sizes, int n_in,
                              void* d_out, int out_size)
{
    const float* x      = (const float*)d_in[0];
    const float* cent   = (const float*)d_in[1];
    const float* weight = (const float*)d_in[2];
    const float* bias   = (const float*)d_in[4];
    float* out = (float*)d_out;

    const int ntok = in_sizes[0] / INF;

    const int IDX_SMEM = IDX_FLOATS * (int)sizeof(float);
    const int G_SMEM   = NC * KC * 32 * (int)sizeof(float) + 256 * NC;

    cudaFuncSetAttribute(idx_kernel,    cudaFuncAttributeMaxDynamicSharedMemorySize, IDX_SMEM);
    cudaFuncSetAttribute(gather_kernel, cudaFuncAttributeMaxDynamicSharedMemorySize, G_SMEM);

    idx_kernel<<<dim3(ntok / 128, NC), 256, IDX_SMEM>>>(x, cent);
    lut_kernel<<<dim3(OF / 128, NC), 512>>>(cent, weight);
    gather_kernel<<<dim3(OF / 32, ntok / 256), 256, G_SMEM>>>(out, bias);
}